// round 10
// baseline (speedup 1.0000x reference)
#include <cuda_runtime.h>
#include <cuda_bf16.h>
#include <cstdint>

// GradientLayerPoisson: tanh-MLP 2->256->256->256->1 second-order jet
// via mma.sync bf16 3-term split GEMMs (hh + hl + lh), fully fused.
// R10: 32 samples/CTA (2 m-tiles), 2 CTAs/SM. H stored k-interleaved so each
// A fragment is 2x LDS.128 (conflict-free). B fragments single-buffered LDG
// from fragment-ordered weight image.

#define HID  256
#define RS   136        // H row stride in 8B {hi,lo} pairs; RS%16==8 -> LDS.128 conflict-free
#define RS4  68         // row stride in uint4

// SMEM byte offsets (96 H rows * 136 pairs * 8B = 104448)
#define SM_H    0
#define SM_BIAS 104448  // [2][256] fp32
#define SM_W4   106496  // [256] fp32
#define SM_X    107520  // [32] float2
#define SM_OUT  107776  // [3][32] fp32
#define SM_TOT  108160

// fragment-ordered weight image: [l][kc][ks][warp][lane][16 words]
//  words 0-3: Bh[nt][0], 4-7: Bh[nt][1], 8-11: Bl[nt][0], 12-15: Bl[nt][1]
__device__ __align__(16) uint32_t g_Wp[2][4][4][8][32][16];

// position of k-pair kp within an H row (interleave: (kp, kp+4) adjacent)
__device__ __forceinline__ int hpos(int kp) {
    return ((kp & ~7) ) + 2 * (kp & 3) + ((kp >> 2) & 1);
}

__device__ __forceinline__ void tanh_d(float x, float& a, float& s2) {
    x = fminf(fmaxf(x, -15.f), 15.f);
    float t = exp2f(x * 2.8853900817779268f);
    float d = 1.f + t, r;
    asm("rcp.approx.ftz.f32 %0, %1;" : "=f"(r) : "f"(d));
    r = r * (2.f - d * r);
    a  = 1.f - 2.f * r;
    s2 = 4.f * r * (1.f - r);
}

__device__ __forceinline__ void pk2(float x, float y, uint32_t& hi, uint32_t& lo) {
    __nv_bfloat16 hx = __float2bfloat16_rn(x);
    __nv_bfloat16 hy = __float2bfloat16_rn(y);
    __nv_bfloat16 lx = __float2bfloat16_rn(x - __bfloat162float(hx));
    __nv_bfloat16 ly = __float2bfloat16_rn(y - __bfloat162float(hy));
    hi = (uint32_t)__bfloat16_as_ushort(hx) | ((uint32_t)__bfloat16_as_ushort(hy) << 16);
    lo = (uint32_t)__bfloat16_as_ushort(lx) | ((uint32_t)__bfloat16_as_ushort(ly) << 16);
}

#define MMA(Dx, A0, A1, A2, A3, B0, B1)                                         \
    asm volatile("mma.sync.aligned.m16n8k16.row.col.f32.bf16.bf16.f32 "         \
                 "{%0,%1,%2,%3},{%4,%5,%6,%7},{%8,%9},{%0,%1,%2,%3};"           \
                 : "+f"((Dx)[0]), "+f"((Dx)[1]), "+f"((Dx)[2]), "+f"((Dx)[3])   \
                 : "r"(A0), "r"(A1), "r"(A2), "r"(A3), "r"(B0), "r"(B1))

// ---- prep: bake W2/W3 into fragment-ordered hi/lo image ----
extern "C" __global__ void prep_w(const float* __restrict__ W2,
                                  const float* __restrict__ W3) {
    const int b = blockIdx.x;                 // 32 blocks: l(2) x kc(4) x ks(4)
    const int l = b >> 4, kc = (b >> 2) & 3, ks = b & 3;
    const int t = threadIdx.x, w = t >> 5, lane = t & 31;
    const float* W = l ? W3 : W2;
    uint32_t* dst = g_Wp[l][kc][ks][w][lane];
    #pragma unroll
    for (int j = 0; j < 2; ++j)
        #pragma unroll
        for (int nt = 0; nt < 4; ++nt) {
            int kp = ks * 8 + (lane & 3) + 4 * j;
            int n  = w * 32 + nt * 8 + (lane >> 2);
            float v0 = W[(kc * 64 + 2 * kp) * HID + n];
            float v1 = W[(kc * 64 + 2 * kp + 1) * HID + n];
            uint32_t h, lo;
            pk2(v0, v1, h, lo);
            dst[nt + 4 * j]     = h;
            dst[8 + nt + 4 * j] = lo;
        }
}

extern "C" __global__ void __launch_bounds__(256, 2)
pinn_mma_kernel(const float* __restrict__ x,
                const float* __restrict__ W1, const float* __restrict__ b1,
                const float* __restrict__ b2, const float* __restrict__ b3,
                const float* __restrict__ W4, const float* __restrict__ b4,
                float* __restrict__ out, int B) {
    extern __shared__ unsigned char smem[];
    uint2*  Hb     = (uint2*)(smem + SM_H);
    float*  biasSm = (float*)(smem + SM_BIAS);
    float*  w4Sm   = (float*)(smem + SM_W4);
    float2* xSm    = (float2*)(smem + SM_X);
    float*  outSm  = (float*)(smem + SM_OUT);

    const int t = threadIdx.x, lane = t & 31, w = t >> 5;
    const int bs = blockIdx.x * 32;
    const int g4 = lane >> 2, tid3 = lane & 3;

    if (t < 96) outSm[t] = 0.f;
    if (t < 32) xSm[t] = ((const float2*)x)[bs + t];
    biasSm[t]       = b2[t];
    biasSm[256 + t] = b3[t];
    w4Sm[t] = W4[t];
    __syncthreads();

    // ---- layer 1: jets into H (z' = W1[0][u], z'' = 0) ----
    {
        const int up = t & 127, sh = t >> 7;
        const int pp = hpos(up);
        float2 c0 = ((const float2*)W1)[up];
        float2 c1 = ((const float2*)(W1 + HID))[up];
        float2 bb = ((const float2*)b1)[up];
        #pragma unroll 4
        for (int i = 0; i < 16; ++i) {
            int s = sh * 16 + i;
            float2 xv = xSm[s];
            float a0, s20, a0b, s21;
            tanh_d(fmaf(xv.x, c0.x, fmaf(xv.y, c1.x, bb.x)), a0, s20);
            tanh_d(fmaf(xv.x, c0.y, fmaf(xv.y, c1.y, bb.y)), a0b, s21);
            float a1u0 = s20 * c0.x, a2u0 = -2.f * a0  * a1u0 * c0.x;
            float a1u1 = s21 * c0.y, a2u1 = -2.f * a0b * a1u1 * c0.y;
            uint32_t h, lo2;
            pk2(a0, a0b, h, lo2);    Hb[(0 * 32 + s) * RS + pp] = make_uint2(h, lo2);
            pk2(a1u0, a1u1, h, lo2); Hb[(1 * 32 + s) * RS + pp] = make_uint2(h, lo2);
            pk2(a2u0, a2u1, h, lo2); Hb[(2 * 32 + s) * RS + pp] = make_uint2(h, lo2);
        }
    }
    __syncthreads();

    float D[3][2][4][4];
    float ps[2][2][3];

    // per-thread A-fragment base (uint4): row g4, k-slot tid3
    const uint4* HbA = (const uint4*)(smem + SM_H) + g4 * RS4 + tid3;

    #pragma unroll 1
    for (int l = 0; l < 2; ++l) {
        #pragma unroll
        for (int a = 0; a < 3; ++a)
            #pragma unroll
            for (int m_ = 0; m_ < 2; ++m_)
                #pragma unroll
                for (int c = 0; c < 4; ++c)
                    #pragma unroll
                    for (int d = 0; d < 4; ++d) D[a][m_][c][d] = 0.f;

        const uint4* wpT = (const uint4*)g_Wp[l] + ((w * 32 + lane) << 2); // +step*1024

        #pragma unroll
        for (int step = 0; step < 16; ++step) {
            uint32_t q[16];
            {
                const uint4* src = wpT + (step << 10);
                *(uint4*)(q + 0)  = src[0];
                *(uint4*)(q + 4)  = src[1];
                *(uint4*)(q + 8)  = src[2];
                *(uint4*)(q + 12) = src[3];
            }
            #pragma unroll
            for (int st = 0; st < 3; ++st) {
                #pragma unroll
                for (int mt = 0; mt < 2; ++mt) {
                    const uint4* hp = HbA + (st * 32 + mt * 16) * RS4 + step * 4;
                    uint4 L0 = hp[0];
                    uint4 L1 = hp[8 * RS4];
                    #pragma unroll
                    for (int nt = 0; nt < 4; ++nt) {
                        MMA(D[st][mt][nt], L0.x, L1.x, L0.z, L1.z, q[nt], q[4 + nt]);
                        MMA(D[st][mt][nt], L0.x, L1.x, L0.z, L1.z, q[8 + nt], q[12 + nt]);
                        MMA(D[st][mt][nt], L0.y, L1.y, L0.w, L1.w, q[nt], q[4 + nt]);
                    }
                }
            }
        }
        __syncthreads();   // all warps done reading H before epilogue rewrites it

        // ---- jet epilogue ----
        if (l == 1) {
            #pragma unroll
            for (int m_ = 0; m_ < 2; ++m_)
                #pragma unroll
                for (int rh = 0; rh < 2; ++rh)
                    #pragma unroll
                    for (int c = 0; c < 3; ++c) ps[m_][rh][c] = 0.f;
        }
        #pragma unroll
        for (int mt = 0; mt < 2; ++mt) {
            #pragma unroll
            for (int nt = 0; nt < 4; ++nt) {
                const int u0 = (w << 5) + (nt << 3) + (tid3 << 1);
                float2 bb  = *(const float2*)(biasSm + (l ? 256 : 0) + u0);
                float2 w4v = *(const float2*)(w4Sm + u0);
                float av[4], a1v[4], a2v[4];
                #pragma unroll
                for (int p_ = 0; p_ < 4; ++p_) {
                    float z  = D[0][mt][nt][p_] + ((p_ & 1) ? bb.y : bb.x);
                    float z1 = D[1][mt][nt][p_];
                    float z2 = D[2][mt][nt][p_];
                    float a, s2;
                    tanh_d(z, a, s2);
                    av[p_]  = a;
                    a1v[p_] = s2 * z1;
                    a2v[p_] = s2 * z2 - 2.f * a * a1v[p_] * z1;
                }
                if (l == 0) {
                    const int r0 = mt * 16 + g4;
                    // k-pair index pi = w*16 + nt*4 + tid3; interleaved position:
                    const int pp = 16 * w + 8 * (nt >> 1) + (nt & 1) + 2 * tid3;
                    uint32_t h, lo2;
                    pk2(av[0],  av[1],  h, lo2); Hb[(0*32 + r0    ) * RS + pp] = make_uint2(h, lo2);
                    pk2(av[2],  av[3],  h, lo2); Hb[(0*32 + r0 + 8) * RS + pp] = make_uint2(h, lo2);
                    pk2(a1v[0], a1v[1], h, lo2); Hb[(1*32 + r0    ) * RS + pp] = make_uint2(h, lo2);
                    pk2(a1v[2], a1v[3], h, lo2); Hb[(1*32 + r0 + 8) * RS + pp] = make_uint2(h, lo2);
                    pk2(a2v[0], a2v[1], h, lo2); Hb[(2*32 + r0    ) * RS + pp] = make_uint2(h, lo2);
                    pk2(a2v[2], a2v[3], h, lo2); Hb[(2*32 + r0 + 8) * RS + pp] = make_uint2(h, lo2);
                } else {
                    #pragma unroll
                    for (int p_ = 0; p_ < 4; ++p_) {
                        float wv = (p_ & 1) ? w4v.y : w4v.x;
                        int rh = p_ >> 1;
                        ps[mt][rh][0] += av[p_]  * wv;
                        ps[mt][rh][1] += a1v[p_] * wv;
                        ps[mt][rh][2] += a2v[p_] * wv;
                    }
                }
            }
        }
        if (l == 0) {
            __syncthreads();           // H fully rewritten before layer-2 MMAs
        } else {
            #pragma unroll
            for (int mt = 0; mt < 2; ++mt)
                #pragma unroll
                for (int rh = 0; rh < 2; ++rh)
                    #pragma unroll
                    for (int st = 0; st < 3; ++st) {
                        float v = ps[mt][rh][st];
                        v += __shfl_xor_sync(0xffffffffu, v, 1);
                        v += __shfl_xor_sync(0xffffffffu, v, 2);
                        if (tid3 == 0)
                            atomicAdd(&outSm[st * 32 + mt * 16 + g4 + rh * 8], v);
                    }
        }
    }

    __syncthreads();
    if (t < 96) {
        int st = t >> 5, s = t & 31;
        float v = outSm[t] + (st == 0 ? b4[0] : 0.f);
        out[st * B + bs + s] = v;
    }
}

extern "C" void kernel_launch(void* const* d_in, const int* in_sizes, int n_in,
                              void* d_out, int out_size) {
    const float* x  = (const float*)d_in[0];
    const float* W1 = (const float*)d_in[1];
    const float* b1 = (const float*)d_in[2];
    const float* W2 = (const float*)d_in[3];
    const float* b2 = (const float*)d_in[4];
    const float* W3 = (const float*)d_in[5];
    const float* b3 = (const float*)d_in[6];
    const float* W4 = (const float*)d_in[7];
    const float* b4 = (const float*)d_in[8];
    float* out = (float*)d_out;
    const int B = in_sizes[0] / 2;

    prep_w<<<32, 256>>>(W2, W3);

    cudaFuncSetAttribute(pinn_mma_kernel,
                         cudaFuncAttributeMaxDynamicSharedMemorySize, SM_TOT);
    pinn_mma_kernel<<<B / 32, 256, SM_TOT>>>(x, W1, b1, b2, b3, W4, b4, out, B);
}

// round 11
// speedup vs baseline: 1.1638x; 1.1638x over previous
#include <cuda_runtime.h>
#include <cuda_bf16.h>
#include <cstdint>

// GradientLayerPoisson: tanh-MLP 2->256->256->256->1 second-order jet
// via mma.sync bf16 3-term split GEMMs (hh + hl + lh), fully fused.
// R11: R9 structure (16 samples/CTA, 2 CTAs/SM, unrolled k-loop, double-
// buffered B prefetch) + k-interleaved H layout so each A fragment is
// 2x LDS.128 (conflict-free, RS4=68).

#define HID  256
#define RS   136        // H row stride in 8B {hi,lo} pairs
#define RS4  68         // row stride in uint4 (68*16 % 128 == 16B*... conflict-free)

// SMEM byte offsets (48 H rows * 136 pairs * 8B = 52224)
#define SM_H    0
#define SM_BIAS 52224   // [2][256] fp32
#define SM_W4   54272   // [256] fp32
#define SM_X    55296   // [16] float2
#define SM_OUT  55424   // [3][16] fp32
#define SM_TOT  55616

// fragment-ordered weight image: [l][kc][ks][warp][lane][16 words]
//  words 0-3: Bh[nt][0], 4-7: Bh[nt][1], 8-11: Bl[nt][0], 12-15: Bl[nt][1]
__device__ __align__(16) uint32_t g_Wp[2][4][4][8][32][16];

// position of k-pair kp within an H row (interleave: (kp, kp+4) adjacent)
__device__ __forceinline__ int hpos(int kp) {
    return (kp & ~7) + 2 * (kp & 3) + ((kp >> 2) & 1);
}

__device__ __forceinline__ void tanh_d(float x, float& a, float& s2) {
    x = fminf(fmaxf(x, -15.f), 15.f);
    float t = exp2f(x * 2.8853900817779268f);
    float d = 1.f + t, r;
    asm("rcp.approx.ftz.f32 %0, %1;" : "=f"(r) : "f"(d));
    r = r * (2.f - d * r);
    a  = 1.f - 2.f * r;
    s2 = 4.f * r * (1.f - r);
}

__device__ __forceinline__ void pk2(float x, float y, uint32_t& hi, uint32_t& lo) {
    __nv_bfloat16 hx = __float2bfloat16_rn(x);
    __nv_bfloat16 hy = __float2bfloat16_rn(y);
    __nv_bfloat16 lx = __float2bfloat16_rn(x - __bfloat162float(hx));
    __nv_bfloat16 ly = __float2bfloat16_rn(y - __bfloat162float(hy));
    hi = (uint32_t)__bfloat16_as_ushort(hx) | ((uint32_t)__bfloat16_as_ushort(hy) << 16);
    lo = (uint32_t)__bfloat16_as_ushort(lx) | ((uint32_t)__bfloat16_as_ushort(ly) << 16);
}

#define MMA(Dx, A0, A1, A2, A3, B0, B1)                                         \
    asm volatile("mma.sync.aligned.m16n8k16.row.col.f32.bf16.bf16.f32 "         \
                 "{%0,%1,%2,%3},{%4,%5,%6,%7},{%8,%9},{%0,%1,%2,%3};"           \
                 : "+f"((Dx)[0]), "+f"((Dx)[1]), "+f"((Dx)[2]), "+f"((Dx)[3])   \
                 : "r"(A0), "r"(A1), "r"(A2), "r"(A3), "r"(B0), "r"(B1))

// ---- prep: bake W2/W3 into fragment-ordered hi/lo image ----
extern "C" __global__ void prep_w(const float* __restrict__ W2,
                                  const float* __restrict__ W3) {
    const int b = blockIdx.x;                 // 32 blocks: l(2) x kc(4) x ks(4)
    const int l = b >> 4, kc = (b >> 2) & 3, ks = b & 3;
    const int t = threadIdx.x, w = t >> 5, lane = t & 31;
    const float* W = l ? W3 : W2;
    uint32_t* dst = g_Wp[l][kc][ks][w][lane];
    #pragma unroll
    for (int j = 0; j < 2; ++j)
        #pragma unroll
        for (int nt = 0; nt < 4; ++nt) {
            int kp = ks * 8 + (lane & 3) + 4 * j;
            int n  = w * 32 + nt * 8 + (lane >> 2);
            float v0 = W[(kc * 64 + 2 * kp) * HID + n];
            float v1 = W[(kc * 64 + 2 * kp + 1) * HID + n];
            uint32_t h, lo;
            pk2(v0, v1, h, lo);
            dst[nt + 4 * j]     = h;
            dst[8 + nt + 4 * j] = lo;
        }
}

extern "C" __global__ void __launch_bounds__(256, 2)
pinn_mma_kernel(const float* __restrict__ x,
                const float* __restrict__ W1, const float* __restrict__ b1,
                const float* __restrict__ b2, const float* __restrict__ b3,
                const float* __restrict__ W4, const float* __restrict__ b4,
                float* __restrict__ out, int B) {
    extern __shared__ unsigned char smem[];
    uint2*  Hb     = (uint2*)(smem + SM_H);
    float*  biasSm = (float*)(smem + SM_BIAS);
    float*  w4Sm   = (float*)(smem + SM_W4);
    float2* xSm    = (float2*)(smem + SM_X);
    float*  outSm  = (float*)(smem + SM_OUT);

    const int t = threadIdx.x, lane = t & 31, w = t >> 5;
    const int bs = blockIdx.x * 16;
    const int g4 = lane >> 2, tid3 = lane & 3;

    if (t < 48) outSm[t] = 0.f;
    if (t < 16) xSm[t] = ((const float2*)x)[bs + t];
    biasSm[t]       = b2[t];
    biasSm[256 + t] = b3[t];
    w4Sm[t] = W4[t];
    __syncthreads();

    // ---- layer 1: jets into H (z' = W1[0][u], z'' = 0) ----
    {
        const int up = t & 127, sh = t >> 7;
        const int pp = hpos(up);
        float2 c0 = ((const float2*)W1)[up];
        float2 c1 = ((const float2*)(W1 + HID))[up];
        float2 bb = ((const float2*)b1)[up];
        #pragma unroll 4
        for (int i = 0; i < 8; ++i) {
            int s = sh * 8 + i;
            float2 xv = xSm[s];
            float a0, s20, a0b, s21;
            tanh_d(fmaf(xv.x, c0.x, fmaf(xv.y, c1.x, bb.x)), a0, s20);
            tanh_d(fmaf(xv.x, c0.y, fmaf(xv.y, c1.y, bb.y)), a0b, s21);
            float a1u0 = s20 * c0.x, a2u0 = -2.f * a0  * a1u0 * c0.x;
            float a1u1 = s21 * c0.y, a2u1 = -2.f * a0b * a1u1 * c0.y;
            uint32_t h, lo2;
            pk2(a0, a0b, h, lo2);    Hb[(0 * 16 + s) * RS + pp] = make_uint2(h, lo2);
            pk2(a1u0, a1u1, h, lo2); Hb[(1 * 16 + s) * RS + pp] = make_uint2(h, lo2);
            pk2(a2u0, a2u1, h, lo2); Hb[(2 * 16 + s) * RS + pp] = make_uint2(h, lo2);
        }
    }
    __syncthreads();

    float D[3][4][4];
    float ps[2][3];

    // per-thread A-fragment base (uint4): row g4, k-slot tid3
    const uint4* HbA = (const uint4*)(smem + SM_H) + g4 * RS4 + tid3;

    #pragma unroll 1
    for (int l = 0; l < 2; ++l) {
        #pragma unroll
        for (int a = 0; a < 3; ++a)
            #pragma unroll
            for (int c = 0; c < 4; ++c)
                #pragma unroll
                for (int d = 0; d < 4; ++d) D[a][c][d] = 0.f;

        const uint4* wpT = (const uint4*)g_Wp[l] + ((w * 32 + lane) << 2); // +step*1024
        uint32_t q[2][16];
        *(uint4*)(q[0] + 0)  = wpT[0];
        *(uint4*)(q[0] + 4)  = wpT[1];
        *(uint4*)(q[0] + 8)  = wpT[2];
        *(uint4*)(q[0] + 12) = wpT[3];

        #pragma unroll
        for (int step = 0; step < 16; ++step) {
            const int cur = step & 1, nxt = cur ^ 1;
            if (step < 15) {
                const uint4* src = wpT + ((step + 1) << 10);
                *(uint4*)(q[nxt] + 0)  = src[0];
                *(uint4*)(q[nxt] + 4)  = src[1];
                *(uint4*)(q[nxt] + 8)  = src[2];
                *(uint4*)(q[nxt] + 12) = src[3];
            }
            #pragma unroll
            for (int st = 0; st < 3; ++st) {
                const uint4* hp = HbA + st * (16 * RS4) + step * 4;
                uint4 L0 = hp[0];
                uint4 L1 = hp[8 * RS4];
                #pragma unroll
                for (int nt = 0; nt < 4; ++nt) {
                    MMA(D[st][nt], L0.x, L1.x, L0.z, L1.z, q[cur][nt], q[cur][4 + nt]);
                    MMA(D[st][nt], L0.x, L1.x, L0.z, L1.z, q[cur][8 + nt], q[cur][12 + nt]);
                    MMA(D[st][nt], L0.y, L1.y, L0.w, L1.w, q[cur][nt], q[cur][4 + nt]);
                }
            }
        }
        __syncthreads();   // all warps done reading H before epilogue rewrites it

        // ---- jet epilogue ----
        if (l == 1) {
            #pragma unroll
            for (int a = 0; a < 2; ++a)
                #pragma unroll
                for (int c = 0; c < 3; ++c) ps[a][c] = 0.f;
        }
        #pragma unroll
        for (int nt = 0; nt < 4; ++nt) {
            const int u0 = (w << 5) + (nt << 3) + (tid3 << 1);
            float2 bb  = *(const float2*)(biasSm + (l ? 256 : 0) + u0);
            float2 w4v = *(const float2*)(w4Sm + u0);
            float av[4], a1v[4], a2v[4];
            #pragma unroll
            for (int p_ = 0; p_ < 4; ++p_) {
                float z  = D[0][nt][p_] + ((p_ & 1) ? bb.y : bb.x);
                float z1 = D[1][nt][p_];
                float z2 = D[2][nt][p_];
                float a, s2;
                tanh_d(z, a, s2);
                av[p_]  = a;
                a1v[p_] = s2 * z1;
                a2v[p_] = s2 * z2 - 2.f * a * a1v[p_] * z1;
            }
            if (l == 0) {
                // k-pair index pi = w*16 + nt*4 + tid3 -> interleaved position
                const int pp = 16 * w + 8 * (nt >> 1) + (nt & 1) + 2 * tid3;
                uint32_t h, lo2;
                pk2(av[0],  av[1],  h, lo2); Hb[(0*16 + g4    ) * RS + pp] = make_uint2(h, lo2);
                pk2(av[2],  av[3],  h, lo2); Hb[(0*16 + g4 + 8) * RS + pp] = make_uint2(h, lo2);
                pk2(a1v[0], a1v[1], h, lo2); Hb[(1*16 + g4    ) * RS + pp] = make_uint2(h, lo2);
                pk2(a1v[2], a1v[3], h, lo2); Hb[(1*16 + g4 + 8) * RS + pp] = make_uint2(h, lo2);
                pk2(a2v[0], a2v[1], h, lo2); Hb[(2*16 + g4    ) * RS + pp] = make_uint2(h, lo2);
                pk2(a2v[2], a2v[3], h, lo2); Hb[(2*16 + g4 + 8) * RS + pp] = make_uint2(h, lo2);
            } else {
                #pragma unroll
                for (int p_ = 0; p_ < 4; ++p_) {
                    float wv = (p_ & 1) ? w4v.y : w4v.x;
                    int rh = p_ >> 1;
                    ps[rh][0] += av[p_]  * wv;
                    ps[rh][1] += a1v[p_] * wv;
                    ps[rh][2] += a2v[p_] * wv;
                }
            }
        }
        if (l == 0) {
            __syncthreads();           // H fully rewritten before layer-2 MMAs
        } else {
            #pragma unroll
            for (int rh = 0; rh < 2; ++rh)
                #pragma unroll
                for (int st = 0; st < 3; ++st) {
                    float v = ps[rh][st];
                    v += __shfl_xor_sync(0xffffffffu, v, 1);
                    v += __shfl_xor_sync(0xffffffffu, v, 2);
                    if (tid3 == 0)
                        atomicAdd(&outSm[st * 16 + g4 + rh * 8], v);
                }
        }
    }

    __syncthreads();
    if (t < 48) {
        int st = t >> 4, s = t & 15;
        float v = outSm[t] + (st == 0 ? b4[0] : 0.f);
        out[st * B + bs + s] = v;
    }
}

extern "C" void kernel_launch(void* const* d_in, const int* in_sizes, int n_in,
                              void* d_out, int out_size) {
    const float* x  = (const float*)d_in[0];
    const float* W1 = (const float*)d_in[1];
    const float* b1 = (const float*)d_in[2];
    const float* W2 = (const float*)d_in[3];
    const float* b2 = (const float*)d_in[4];
    const float* W3 = (const float*)d_in[5];
    const float* b3 = (const float*)d_in[6];
    const float* W4 = (const float*)d_in[7];
    const float* b4 = (const float*)d_in[8];
    float* out = (float*)d_out;
    const int B = in_sizes[0] / 2;

    prep_w<<<32, 256>>>(W2, W3);

    cudaFuncSetAttribute(pinn_mma_kernel,
                         cudaFuncAttributeMaxDynamicSharedMemorySize, SM_TOT);
    pinn_mma_kernel<<<B / 16, 256, SM_TOT>>>(x, W1, b1, b2, b3, W4, b4, out, B);
}

// round 12
// speedup vs baseline: 1.2959x; 1.1136x over previous
#include <cuda_runtime.h>
#include <cuda_bf16.h>
#include <cstdint>

// GradientLayerPoisson: tanh-MLP 2->256->256->256->1 second-order jet
// via mma.sync bf16 3-term split GEMMs (hh + hl + lh), fully fused.
// R12: 128 threads/CTA (4 warps, n=64 per warp), 16 samples/CTA, 3 CTAs/SM.
// A fragments 2x LDS.128 (k-interleaved H); B fragments one uint4 per n-tile
// from a fragment-ordered weight image (contiguous 512B per LDG.128).

#define HID  256
#define RS   136        // H row stride in 8B {hi,lo} pairs
#define RS4  68         // row stride in uint4

// SMEM byte offsets (48 H rows * 136 pairs * 8B = 52224)
#define SM_H    0
#define SM_BIAS 52224   // [2][256] fp32
#define SM_W4   54272   // [256] fp32
#define SM_X    55296   // [16] float2
#define SM_OUT  55424   // [3][16] fp32
#define SM_TOT  55616

// fragment-ordered weight image: [l][step][wq][nt][lane] uint4 = {Bh0,Bh1,Bl0,Bl1}
__device__ __align__(16) uint4 g_Wq[2 * 16 * 4 * 8 * 32];

// position of k-pair kp within an H row (interleave: (kp, kp+4) adjacent)
__device__ __forceinline__ int hpos(int kp) {
    return (kp & ~7) + 2 * (kp & 3) + ((kp >> 2) & 1);
}

__device__ __forceinline__ void tanh_d(float x, float& a, float& s2) {
    x = fminf(fmaxf(x, -15.f), 15.f);
    float t = exp2f(x * 2.8853900817779268f);
    float d = 1.f + t, r;
    asm("rcp.approx.ftz.f32 %0, %1;" : "=f"(r) : "f"(d));
    r = r * (2.f - d * r);
    a  = 1.f - 2.f * r;
    s2 = 4.f * r * (1.f - r);
}

__device__ __forceinline__ void pk2(float x, float y, uint32_t& hi, uint32_t& lo) {
    __nv_bfloat16 hx = __float2bfloat16_rn(x);
    __nv_bfloat16 hy = __float2bfloat16_rn(y);
    __nv_bfloat16 lx = __float2bfloat16_rn(x - __bfloat162float(hx));
    __nv_bfloat16 ly = __float2bfloat16_rn(y - __bfloat162float(hy));
    hi = (uint32_t)__bfloat16_as_ushort(hx) | ((uint32_t)__bfloat16_as_ushort(hy) << 16);
    lo = (uint32_t)__bfloat16_as_ushort(lx) | ((uint32_t)__bfloat16_as_ushort(ly) << 16);
}

#define MMA(Dx, A0, A1, A2, A3, B0, B1)                                         \
    asm volatile("mma.sync.aligned.m16n8k16.row.col.f32.bf16.bf16.f32 "         \
                 "{%0,%1,%2,%3},{%4,%5,%6,%7},{%8,%9},{%0,%1,%2,%3};"           \
                 : "+f"((Dx)[0]), "+f"((Dx)[1]), "+f"((Dx)[2]), "+f"((Dx)[3])   \
                 : "r"(A0), "r"(A1), "r"(A2), "r"(A3), "r"(B0), "r"(B1))

// ---- prep: bake W2/W3 into fragment-ordered hi/lo image ----
extern "C" __global__ void prep_w(const float* __restrict__ W2,
                                  const float* __restrict__ W3) {
    const int b = blockIdx.x;                 // 32 blocks: l(2) x kc(4) x ks(4)
    const int l = b >> 4, kc = (b >> 2) & 3, ks = b & 3;
    const int step = kc * 4 + ks;
    const int t = threadIdx.x, wq = t >> 5, lane = t & 31;
    const int g4 = lane >> 2, tid3 = lane & 3;
    const float* W = l ? W3 : W2;
    #pragma unroll
    for (int nt = 0; nt < 8; ++nt) {
        int n = wq * 64 + nt * 8 + g4;
        int kpA = ks * 8 + tid3;       // j = 0
        int kpB = kpA + 4;             // j = 1
        uint32_t h0, l0, h1, l1;
        pk2(W[(kc * 64 + 2 * kpA) * HID + n], W[(kc * 64 + 2 * kpA + 1) * HID + n], h0, l0);
        pk2(W[(kc * 64 + 2 * kpB) * HID + n], W[(kc * 64 + 2 * kpB + 1) * HID + n], h1, l1);
        g_Wq[(((l * 16 + step) * 4 + wq) * 8 + nt) * 32 + lane] =
            make_uint4(h0, h1, l0, l1);
    }
}

extern "C" __global__ void __launch_bounds__(128, 3)
pinn_mma_kernel(const float* __restrict__ x,
                const float* __restrict__ W1, const float* __restrict__ b1,
                const float* __restrict__ b2, const float* __restrict__ b3,
                const float* __restrict__ W4, const float* __restrict__ b4,
                float* __restrict__ out, int B) {
    extern __shared__ unsigned char smem[];
    uint2*  Hb     = (uint2*)(smem + SM_H);
    float*  biasSm = (float*)(smem + SM_BIAS);
    float*  w4Sm   = (float*)(smem + SM_W4);
    float2* xSm    = (float2*)(smem + SM_X);
    float*  outSm  = (float*)(smem + SM_OUT);

    const int t = threadIdx.x, lane = t & 31, w = t >> 5;
    const int bs = blockIdx.x * 16;
    const int g4 = lane >> 2, tid3 = lane & 3;

    if (t < 48) outSm[t] = 0.f;
    if (t < 16) xSm[t] = ((const float2*)x)[bs + t];
    #pragma unroll
    for (int i = 0; i < 2; ++i) {
        biasSm[t + 128 * i]       = b2[t + 128 * i];
        biasSm[256 + t + 128 * i] = b3[t + 128 * i];
        w4Sm[t + 128 * i]         = W4[t + 128 * i];
    }
    __syncthreads();

    // ---- layer 1: jets into H (z' = W1[0][u], z'' = 0) ----
    {
        const int up = t;              // unit pair 0..127
        const int pp = hpos(up);
        float2 c0 = ((const float2*)W1)[up];
        float2 c1 = ((const float2*)(W1 + HID))[up];
        float2 bb = ((const float2*)b1)[up];
        #pragma unroll 4
        for (int s = 0; s < 16; ++s) {
            float2 xv = xSm[s];
            float a0, s20, a0b, s21;
            tanh_d(fmaf(xv.x, c0.x, fmaf(xv.y, c1.x, bb.x)), a0, s20);
            tanh_d(fmaf(xv.x, c0.y, fmaf(xv.y, c1.y, bb.y)), a0b, s21);
            float a1u0 = s20 * c0.x, a2u0 = -2.f * a0  * a1u0 * c0.x;
            float a1u1 = s21 * c0.y, a2u1 = -2.f * a0b * a1u1 * c0.y;
            uint32_t h, lo2;
            pk2(a0, a0b, h, lo2);    Hb[(0 * 16 + s) * RS + pp] = make_uint2(h, lo2);
            pk2(a1u0, a1u1, h, lo2); Hb[(1 * 16 + s) * RS + pp] = make_uint2(h, lo2);
            pk2(a2u0, a2u1, h, lo2); Hb[(2 * 16 + s) * RS + pp] = make_uint2(h, lo2);
        }
    }
    __syncthreads();

    float D[3][8][4];
    float ps[2][3];

    // per-thread A-fragment base (uint4): row g4, k-slot tid3
    const uint4* HbA = (const uint4*)(smem + SM_H) + g4 * RS4 + tid3;

    #pragma unroll 1
    for (int l = 0; l < 2; ++l) {
        #pragma unroll
        for (int a = 0; a < 3; ++a)
            #pragma unroll
            for (int c = 0; c < 8; ++c)
                #pragma unroll
                for (int d = 0; d < 4; ++d) D[a][c][d] = 0.f;

        // per-(warp,lane) B base; step stride = 4*8*32 = 1024 uint4, nt stride = 32
        const uint4* wpT = g_Wq + ((l * 16) * 4 + w) * (8 * 32) + lane;

        #pragma unroll
        for (int step = 0; step < 16; ++step) {
            uint4 qb[8];
            #pragma unroll
            for (int nt = 0; nt < 8; ++nt)
                qb[nt] = wpT[step * 1024 + nt * 32];
            #pragma unroll
            for (int st = 0; st < 3; ++st) {
                const uint4* hp = HbA + st * (16 * RS4) + step * 4;
                uint4 L0 = hp[0];
                uint4 L1 = hp[8 * RS4];
                #pragma unroll
                for (int nt = 0; nt < 8; ++nt) {
                    MMA(D[st][nt], L0.x, L1.x, L0.z, L1.z, qb[nt].x, qb[nt].y);
                    MMA(D[st][nt], L0.x, L1.x, L0.z, L1.z, qb[nt].z, qb[nt].w);
                    MMA(D[st][nt], L0.y, L1.y, L0.w, L1.w, qb[nt].x, qb[nt].y);
                }
            }
        }
        __syncthreads();   // all warps done reading H before epilogue rewrites it

        // ---- jet epilogue ----
        if (l == 1) {
            #pragma unroll
            for (int a = 0; a < 2; ++a)
                #pragma unroll
                for (int c = 0; c < 3; ++c) ps[a][c] = 0.f;
        }
        #pragma unroll
        for (int nt = 0; nt < 8; ++nt) {
            const int u0 = (w << 6) + (nt << 3) + (tid3 << 1);
            float2 bb  = *(const float2*)(biasSm + (l ? 256 : 0) + u0);
            float2 w4v = *(const float2*)(w4Sm + u0);
            float av[4], a1v[4], a2v[4];
            #pragma unroll
            for (int p_ = 0; p_ < 4; ++p_) {
                float z  = D[0][nt][p_] + ((p_ & 1) ? bb.y : bb.x);
                float z1 = D[1][nt][p_];
                float z2 = D[2][nt][p_];
                float a, s2;
                tanh_d(z, a, s2);
                av[p_]  = a;
                a1v[p_] = s2 * z1;
                a2v[p_] = s2 * z2 - 2.f * a * a1v[p_] * z1;
            }
            if (l == 0) {
                const int pi = (w << 5) + (nt << 2) + tid3;   // k-pair index
                const int pp = hpos(pi);
                uint32_t h, lo2;
                pk2(av[0],  av[1],  h, lo2); Hb[(0*16 + g4    ) * RS + pp] = make_uint2(h, lo2);
                pk2(av[2],  av[3],  h, lo2); Hb[(0*16 + g4 + 8) * RS + pp] = make_uint2(h, lo2);
                pk2(a1v[0], a1v[1], h, lo2); Hb[(1*16 + g4    ) * RS + pp] = make_uint2(h, lo2);
                pk2(a1v[2], a1v[3], h, lo2); Hb[(1*16 + g4 + 8) * RS + pp] = make_uint2(h, lo2);
                pk2(a2v[0], a2v[1], h, lo2); Hb[(2*16 + g4    ) * RS + pp] = make_uint2(h, lo2);
                pk2(a2v[2], a2v[3], h, lo2); Hb[(2*16 + g4 + 8) * RS + pp] = make_uint2(h, lo2);
            } else {
                #pragma unroll
                for (int p_ = 0; p_ < 4; ++p_) {
                    float wv = (p_ & 1) ? w4v.y : w4v.x;
                    int rh = p_ >> 1;
                    ps[rh][0] += av[p_]  * wv;
                    ps[rh][1] += a1v[p_] * wv;
                    ps[rh][2] += a2v[p_] * wv;
                }
            }
        }
        if (l == 0) {
            __syncthreads();           // H fully rewritten before layer-2 MMAs
        } else {
            #pragma unroll
            for (int rh = 0; rh < 2; ++rh)
                #pragma unroll
                for (int st = 0; st < 3; ++st) {
                    float v = ps[rh][st];
                    v += __shfl_xor_sync(0xffffffffu, v, 1);
                    v += __shfl_xor_sync(0xffffffffu, v, 2);
                    if (tid3 == 0)
                        atomicAdd(&outSm[st * 16 + g4 + rh * 8], v);
                }
        }
    }

    __syncthreads();
    if (t < 48) {
        int st = t >> 4, s = t & 15;
        float v = outSm[t] + (st == 0 ? b4[0] : 0.f);
        out[st * B + bs + s] = v;
    }
}

extern "C" void kernel_launch(void* const* d_in, const int* in_sizes, int n_in,
                              void* d_out, int out_size) {
    const float* x  = (const float*)d_in[0];
    const float* W1 = (const float*)d_in[1];
    const float* b1 = (const float*)d_in[2];
    const float* W2 = (const float*)d_in[3];
    const float* b2 = (const float*)d_in[4];
    const float* W3 = (const float*)d_in[5];
    const float* b3 = (const float*)d_in[6];
    const float* W4 = (const float*)d_in[7];
    const float* b4 = (const float*)d_in[8];
    float* out = (float*)d_out;
    const int B = in_sizes[0] / 2;

    prep_w<<<32, 128>>>(W2, W3);

    cudaFuncSetAttribute(pinn_mma_kernel,
                         cudaFuncAttributeMaxDynamicSharedMemorySize, SM_TOT);
    pinn_mma_kernel<<<B / 16, 128, SM_TOT>>>(x, W1, b1, b2, b3, W4, b4, out, B);
}

// round 13
// speedup vs baseline: 1.3231x; 1.0210x over previous
#include <cuda_runtime.h>
#include <cuda_bf16.h>
#include <cstdint>

// GradientLayerPoisson: tanh-MLP 2->256->256->256->1 second-order jet
// via mma.sync bf16 3-term split GEMMs (hh + hl + lh), fully fused.
// R13: R12 structure (128 thr/CTA, 4 warps n=64, 16 samples/CTA, 3 CTAs/SM)
// with pk2 rebuilt on cvt.rn.bf16x2.f32 (1 packed cvt per word, residual
// re-expansion via shift/mask) -> ~half the ALU in seeds/epilogues.

#define HID  256
#define RS   136        // H row stride in 8B {hi,lo} pairs
#define RS4  68         // row stride in uint4

// SMEM byte offsets (48 H rows * 136 pairs * 8B = 52224)
#define SM_H    0
#define SM_BIAS 52224   // [2][256] fp32
#define SM_W4   54272   // [256] fp32
#define SM_X    55296   // [16] float2
#define SM_OUT  55424   // [3][16] fp32
#define SM_TOT  55616

// fragment-ordered weight image: [l][step][wq][nt][lane] uint4 = {Bh0,Bh1,Bl0,Bl1}
__device__ __align__(16) uint4 g_Wq[2 * 16 * 4 * 8 * 32];

// position of k-pair kp within an H row (interleave: (kp, kp+4) adjacent)
__device__ __forceinline__ int hpos(int kp) {
    return (kp & ~7) + 2 * (kp & 3) + ((kp >> 2) & 1);
}

__device__ __forceinline__ void tanh_d(float x, float& a, float& s2) {
    x = fminf(fmaxf(x, -15.f), 15.f);
    float t = exp2f(x * 2.8853900817779268f);
    float d = 1.f + t, r;
    asm("rcp.approx.ftz.f32 %0, %1;" : "=f"(r) : "f"(d));
    r = r * (2.f - d * r);
    a  = 1.f - 2.f * r;
    s2 = 4.f * r * (1.f - r);
}

// pack (x,y) -> hi word {bf16(x),bf16(y)} and lo word of residuals
// via packed bf16x2 converts: cvt d,a,b => d.hi=bf16(a), d.lo=bf16(b)
__device__ __forceinline__ void pk2(float x, float y, uint32_t& hi, uint32_t& lo) {
    uint32_t h;
    asm("cvt.rn.bf16x2.f32 %0, %1, %2;" : "=r"(h) : "f"(y), "f"(x));
    float fx = __uint_as_float(h << 16);
    float fy = __uint_as_float(h & 0xffff0000u);
    uint32_t l_;
    asm("cvt.rn.bf16x2.f32 %0, %1, %2;" : "=r"(l_) : "f"(y - fy), "f"(x - fx));
    hi = h; lo = l_;
}

#define MMA(Dx, A0, A1, A2, A3, B0, B1)                                         \
    asm volatile("mma.sync.aligned.m16n8k16.row.col.f32.bf16.bf16.f32 "         \
                 "{%0,%1,%2,%3},{%4,%5,%6,%7},{%8,%9},{%0,%1,%2,%3};"           \
                 : "+f"((Dx)[0]), "+f"((Dx)[1]), "+f"((Dx)[2]), "+f"((Dx)[3])   \
                 : "r"(A0), "r"(A1), "r"(A2), "r"(A3), "r"(B0), "r"(B1))

// ---- prep: bake W2/W3 into fragment-ordered hi/lo image ----
extern "C" __global__ void prep_w(const float* __restrict__ W2,
                                  const float* __restrict__ W3) {
    const int b = blockIdx.x;                 // 32 blocks: l(2) x kc(4) x ks(4)
    const int l = b >> 4, kc = (b >> 2) & 3, ks = b & 3;
    const int step = kc * 4 + ks;
    const int t = threadIdx.x, wq = t >> 5, lane = t & 31;
    const int g4 = lane >> 2, tid3 = lane & 3;
    const float* W = l ? W3 : W2;
    #pragma unroll
    for (int nt = 0; nt < 8; ++nt) {
        int n = wq * 64 + nt * 8 + g4;
        int kpA = ks * 8 + tid3;       // j = 0
        int kpB = kpA + 4;             // j = 1
        uint32_t h0, l0, h1, l1;
        pk2(W[(kc * 64 + 2 * kpA) * HID + n], W[(kc * 64 + 2 * kpA + 1) * HID + n], h0, l0);
        pk2(W[(kc * 64 + 2 * kpB) * HID + n], W[(kc * 64 + 2 * kpB + 1) * HID + n], h1, l1);
        g_Wq[(((l * 16 + step) * 4 + wq) * 8 + nt) * 32 + lane] =
            make_uint4(h0, h1, l0, l1);
    }
}

extern "C" __global__ void __launch_bounds__(128, 3)
pinn_mma_kernel(const float* __restrict__ x,
                const float* __restrict__ W1, const float* __restrict__ b1,
                const float* __restrict__ b2, const float* __restrict__ b3,
                const float* __restrict__ W4, const float* __restrict__ b4,
                float* __restrict__ out, int B) {
    extern __shared__ unsigned char smem[];
    uint2*  Hb     = (uint2*)(smem + SM_H);
    float*  biasSm = (float*)(smem + SM_BIAS);
    float*  w4Sm   = (float*)(smem + SM_W4);
    float2* xSm    = (float2*)(smem + SM_X);
    float*  outSm  = (float*)(smem + SM_OUT);

    const int t = threadIdx.x, lane = t & 31, w = t >> 5;
    const int bs = blockIdx.x * 16;
    const int g4 = lane >> 2, tid3 = lane & 3;

    if (t < 48) outSm[t] = 0.f;
    if (t < 16) xSm[t] = ((const float2*)x)[bs + t];
    #pragma unroll
    for (int i = 0; i < 2; ++i) {
        biasSm[t + 128 * i]       = b2[t + 128 * i];
        biasSm[256 + t + 128 * i] = b3[t + 128 * i];
        w4Sm[t + 128 * i]         = W4[t + 128 * i];
    }
    __syncthreads();

    // ---- layer 1: jets into H (z' = W1[0][u], z'' = 0) ----
    {
        const int up = t;              // unit pair 0..127
        const int pp = hpos(up);
        float2 c0 = ((const float2*)W1)[up];
        float2 c1 = ((const float2*)(W1 + HID))[up];
        float2 bb = ((const float2*)b1)[up];
        #pragma unroll 4
        for (int s = 0; s < 16; ++s) {
            float2 xv = xSm[s];
            float a0, s20, a0b, s21;
            tanh_d(fmaf(xv.x, c0.x, fmaf(xv.y, c1.x, bb.x)), a0, s20);
            tanh_d(fmaf(xv.x, c0.y, fmaf(xv.y, c1.y, bb.y)), a0b, s21);
            float a1u0 = s20 * c0.x, a2u0 = -2.f * a0  * a1u0 * c0.x;
            float a1u1 = s21 * c0.y, a2u1 = -2.f * a0b * a1u1 * c0.y;
            uint32_t h, lo2;
            pk2(a0, a0b, h, lo2);    Hb[(0 * 16 + s) * RS + pp] = make_uint2(h, lo2);
            pk2(a1u0, a1u1, h, lo2); Hb[(1 * 16 + s) * RS + pp] = make_uint2(h, lo2);
            pk2(a2u0, a2u1, h, lo2); Hb[(2 * 16 + s) * RS + pp] = make_uint2(h, lo2);
        }
    }
    __syncthreads();

    float D[3][8][4];
    float ps[2][3];

    // per-thread A-fragment base (uint4): row g4, k-slot tid3
    const uint4* HbA = (const uint4*)(smem + SM_H) + g4 * RS4 + tid3;

    #pragma unroll 1
    for (int l = 0; l < 2; ++l) {
        #pragma unroll
        for (int a = 0; a < 3; ++a)
            #pragma unroll
            for (int c = 0; c < 8; ++c)
                #pragma unroll
                for (int d = 0; d < 4; ++d) D[a][c][d] = 0.f;

        // per-(warp,lane) B base; step stride = 4*8*32 = 1024 uint4, nt stride = 32
        const uint4* wpT = g_Wq + ((l * 16) * 4 + w) * (8 * 32) + lane;

        #pragma unroll
        for (int step = 0; step < 16; ++step) {
            uint4 qb[8];
            #pragma unroll
            for (int nt = 0; nt < 8; ++nt)
                qb[nt] = wpT[step * 1024 + nt * 32];
            #pragma unroll
            for (int st = 0; st < 3; ++st) {
                const uint4* hp = HbA + st * (16 * RS4) + step * 4;
                uint4 L0 = hp[0];
                uint4 L1 = hp[8 * RS4];
                #pragma unroll
                for (int nt = 0; nt < 8; ++nt) {
                    MMA(D[st][nt], L0.x, L1.x, L0.z, L1.z, qb[nt].x, qb[nt].y);
                    MMA(D[st][nt], L0.x, L1.x, L0.z, L1.z, qb[nt].z, qb[nt].w);
                    MMA(D[st][nt], L0.y, L1.y, L0.w, L1.w, qb[nt].x, qb[nt].y);
                }
            }
        }
        __syncthreads();   // all warps done reading H before epilogue rewrites it

        // ---- jet epilogue ----
        if (l == 1) {
            #pragma unroll
            for (int a = 0; a < 2; ++a)
                #pragma unroll
                for (int c = 0; c < 3; ++c) ps[a][c] = 0.f;
        }
        #pragma unroll
        for (int nt = 0; nt < 8; ++nt) {
            const int u0 = (w << 6) + (nt << 3) + (tid3 << 1);
            float2 bb  = *(const float2*)(biasSm + (l ? 256 : 0) + u0);
            float2 w4v = *(const float2*)(w4Sm + u0);
            float av[4], a1v[4], a2v[4];
            #pragma unroll
            for (int p_ = 0; p_ < 4; ++p_) {
                float z  = D[0][nt][p_] + ((p_ & 1) ? bb.y : bb.x);
                float z1 = D[1][nt][p_];
                float z2 = D[2][nt][p_];
                float a, s2;
                tanh_d(z, a, s2);
                av[p_]  = a;
                a1v[p_] = s2 * z1;
                a2v[p_] = s2 * z2 - 2.f * a * a1v[p_] * z1;
            }
            if (l == 0) {
                const int pi = (w << 5) + (nt << 2) + tid3;   // k-pair index
                const int pp = hpos(pi);
                uint32_t h, lo2;
                pk2(av[0],  av[1],  h, lo2); Hb[(0*16 + g4    ) * RS + pp] = make_uint2(h, lo2);
                pk2(av[2],  av[3],  h, lo2); Hb[(0*16 + g4 + 8) * RS + pp] = make_uint2(h, lo2);
                pk2(a1v[0], a1v[1], h, lo2); Hb[(1*16 + g4    ) * RS + pp] = make_uint2(h, lo2);
                pk2(a1v[2], a1v[3], h, lo2); Hb[(1*16 + g4 + 8) * RS + pp] = make_uint2(h, lo2);
                pk2(a2v[0], a2v[1], h, lo2); Hb[(2*16 + g4    ) * RS + pp] = make_uint2(h, lo2);
                pk2(a2v[2], a2v[3], h, lo2); Hb[(2*16 + g4 + 8) * RS + pp] = make_uint2(h, lo2);
            } else {
                #pragma unroll
                for (int p_ = 0; p_ < 4; ++p_) {
                    float wv = (p_ & 1) ? w4v.y : w4v.x;
                    int rh = p_ >> 1;
                    ps[rh][0] += av[p_]  * wv;
                    ps[rh][1] += a1v[p_] * wv;
                    ps[rh][2] += a2v[p_] * wv;
                }
            }
        }
        if (l == 0) {
            __syncthreads();           // H fully rewritten before layer-2 MMAs
        } else {
            #pragma unroll
            for (int rh = 0; rh < 2; ++rh)
                #pragma unroll
                for (int st = 0; st < 3; ++st) {
                    float v = ps[rh][st];
                    v += __shfl_xor_sync(0xffffffffu, v, 1);
                    v += __shfl_xor_sync(0xffffffffu, v, 2);
                    if (tid3 == 0)
                        atomicAdd(&outSm[st * 16 + g4 + rh * 8], v);
                }
        }
    }

    __syncthreads();
    if (t < 48) {
        int st = t >> 4, s = t & 15;
        float v = outSm[t] + (st == 0 ? b4[0] : 0.f);
        out[st * B + bs + s] = v;
    }
}

extern "C" void kernel_launch(void* const* d_in, const int* in_sizes, int n_in,
                              void* d_out, int out_size) {
    const float* x  = (const float*)d_in[0];
    const float* W1 = (const float*)d_in[1];
    const float* b1 = (const float*)d_in[2];
    const float* W2 = (const float*)d_in[3];
    const float* b2 = (const float*)d_in[4];
    const float* W3 = (const float*)d_in[5];
    const float* b3 = (const float*)d_in[6];
    const float* W4 = (const float*)d_in[7];
    const float* b4 = (const float*)d_in[8];
    float* out = (float*)d_out;
    const int B = in_sizes[0] / 2;

    prep_w<<<32, 128>>>(W2, W3);

    cudaFuncSetAttribute(pinn_mma_kernel,
                         cudaFuncAttributeMaxDynamicSharedMemorySize, SM_TOT);
    pinn_mma_kernel<<<B / 16, 128, SM_TOT>>>(x, W1, b1, b2, b3, W4, b4, out, B);
}

// round 15
// speedup vs baseline: 1.5929x; 1.2040x over previous
#include <cuda_runtime.h>
#include <cuda_bf16.h>
#include <cstdint>

// GradientLayerPoisson: tanh-MLP 2->256->256->256->1 second-order jet
// via mma.sync bf16 3-term split GEMMs (hh + hl + lh), fully fused.
// R14: H stored in A-fragment order (AH/AL planes of 16B quads) so each MMA A
// operand is one LDS.128 straight into a contiguous register quad (no operand
// marshaling MOVs). 128 thr/CTA, 4 warps n=64, 16 samples/CTA, 3 CTAs/SM.

#define HID  256

// SMEM byte offsets
#define SM_AH   0        // 3 st x 16 steps x 32 lanes x 16B = 24576
#define SM_AL   24576    // same
#define SM_BIAS 49152    // [2][256] fp32
#define SM_W4   51200    // [256] fp32
#define SM_X    52224    // [16] float2
#define SM_OUT  52352    // [3][16] fp32
#define SM_TOT  52544

// fragment-ordered weight image: [l][step][wq][nt][lane] uint4 = {Bh0,Bh1,Bl0,Bl1}
__device__ __align__(16) uint4 g_Wq[2 * 16 * 4 * 8 * 32];

__device__ __forceinline__ void tanh_d(float x, float& a, float& s2) {
    x = fminf(fmaxf(x, -15.f), 15.f);
    float t = exp2f(x * 2.8853900817779268f);
    float d = 1.f + t, r;
    asm("rcp.approx.ftz.f32 %0, %1;" : "=f"(r) : "f"(d));
    r = r * (2.f - d * r);
    a  = 1.f - 2.f * r;
    s2 = 4.f * r * (1.f - r);
}

// pack (x,y) -> hi word {bf16(x) lo-half, bf16(y) hi-half} and residual lo word
__device__ __forceinline__ void pk2(float x, float y, uint32_t& hi, uint32_t& lo) {
    uint32_t h;
    asm("cvt.rn.bf16x2.f32 %0, %1, %2;" : "=r"(h) : "f"(y), "f"(x));
    float fx = __uint_as_float(h << 16);
    float fy = __uint_as_float(h & 0xffff0000u);
    uint32_t l_;
    asm("cvt.rn.bf16x2.f32 %0, %1, %2;" : "=r"(l_) : "f"(y - fy), "f"(x - fx));
    hi = h; lo = l_;
}

#define MMA(Dx, A0, A1, A2, A3, B0, B1)                                         \
    asm volatile("mma.sync.aligned.m16n8k16.row.col.f32.bf16.bf16.f32 "         \
                 "{%0,%1,%2,%3},{%4,%5,%6,%7},{%8,%9},{%0,%1,%2,%3};"           \
                 : "+f"((Dx)[0]), "+f"((Dx)[1]), "+f"((Dx)[2]), "+f"((Dx)[3])   \
                 : "r"(A0), "r"(A1), "r"(A2), "r"(A3), "r"(B0), "r"(B1))

// ---- prep: bake W2/W3 into fragment-ordered hi/lo image ----
extern "C" __global__ void prep_w(const float* __restrict__ W2,
                                  const float* __restrict__ W3) {
    const int b = blockIdx.x;                 // 32 blocks: l(2) x kc(4) x ks(4)
    const int l = b >> 4, kc = (b >> 2) & 3, ks = b & 3;
    const int step = kc * 4 + ks;
    const int t = threadIdx.x, wq = t >> 5, lane = t & 31;
    const int g4 = lane >> 2, tid3 = lane & 3;
    const float* W = l ? W3 : W2;
    #pragma unroll
    for (int nt = 0; nt < 8; ++nt) {
        int n = wq * 64 + nt * 8 + g4;
        int kpA = ks * 8 + tid3;       // j = 0
        int kpB = kpA + 4;             // j = 1
        uint32_t h0, l0, h1, l1;
        pk2(W[(kc * 64 + 2 * kpA) * HID + n], W[(kc * 64 + 2 * kpA + 1) * HID + n], h0, l0);
        pk2(W[(kc * 64 + 2 * kpB) * HID + n], W[(kc * 64 + 2 * kpB + 1) * HID + n], h1, l1);
        g_Wq[(((l * 16 + step) * 4 + wq) * 8 + nt) * 32 + lane] =
            make_uint4(h0, h1, l0, l1);
    }
}

extern "C" __global__ void __launch_bounds__(128, 3)
pinn_mma_kernel(const float* __restrict__ x,
                const float* __restrict__ W1, const float* __restrict__ b1,
                const float* __restrict__ b2, const float* __restrict__ b3,
                const float* __restrict__ W4, const float* __restrict__ b4,
                float* __restrict__ out, int B) {
    extern __shared__ unsigned char smem[];
    uint32_t* AH     = (uint32_t*)(smem + SM_AH);
    uint32_t* AL     = (uint32_t*)(smem + SM_AL);
    float*    biasSm = (float*)(smem + SM_BIAS);
    float*    w4Sm   = (float*)(smem + SM_W4);
    float2*   xSm    = (float2*)(smem + SM_X);
    float*    outSm  = (float*)(smem + SM_OUT);

    const int t = threadIdx.x, lane = t & 31, w = t >> 5;
    const int bs = blockIdx.x * 16;
    const int g4 = lane >> 2, tid3 = lane & 3;

    if (t < 48) outSm[t] = 0.f;
    if (t < 16) xSm[t] = ((const float2*)x)[bs + t];
    #pragma unroll
    for (int i = 0; i < 2; ++i) {
        biasSm[t + 128 * i]       = b2[t + 128 * i];
        biasSm[256 + t + 128 * i] = b3[t + 128 * i];
        w4Sm[t + 128 * i]         = W4[t + 128 * i];
    }
    __syncthreads();

    // ---- layer 1: jets into fragment-ordered A planes (z' = W1[0][u], z''=0) ----
    {
        const int up = t;                     // k-pair index 0..127
        const int step_t = up >> 3, o = up & 7;
        const int wsel = (o & 4) ? 2 : 0;
        float2 c0 = ((const float2*)W1)[up];
        float2 c1 = ((const float2*)(W1 + HID))[up];
        float2 bb = ((const float2*)b1)[up];
        #pragma unroll 4
        for (int s = 0; s < 16; ++s) {
            float2 xv = xSm[s];
            float a0, s20, a0b, s21;
            tanh_d(fmaf(xv.x, c0.x, fmaf(xv.y, c1.x, bb.x)), a0, s20);
            tanh_d(fmaf(xv.x, c0.y, fmaf(xv.y, c1.y, bb.y)), a0b, s21);
            float a1u0 = s20 * c0.x, a2u0 = -2.f * a0  * a1u0 * c0.x;
            float a1u1 = s21 * c0.y, a2u1 = -2.f * a0b * a1u1 * c0.y;
            const int lane_t = ((s & 7) << 2) | (o & 3);
            const int widx = wsel + (s >> 3);
            const int i0 = ((0 * 16 + step_t) * 32 + lane_t) * 4 + widx;
            const int i1 = ((1 * 16 + step_t) * 32 + lane_t) * 4 + widx;
            const int i2 = ((2 * 16 + step_t) * 32 + lane_t) * 4 + widx;
            uint32_t h, lo2;
            pk2(a0, a0b, h, lo2);    AH[i0] = h; AL[i0] = lo2;
            pk2(a1u0, a1u1, h, lo2); AH[i1] = h; AL[i1] = lo2;
            pk2(a2u0, a2u1, h, lo2); AH[i2] = h; AL[i2] = lo2;
        }
    }
    __syncthreads();

    float D[3][8][4];
    float ps[2][3];

    const uint4* AHq = (const uint4*)(smem + SM_AH) + lane;  // + (st*16+step)*32
    const uint4* ALq = (const uint4*)(smem + SM_AL) + lane;

    #pragma unroll 1
    for (int l = 0; l < 2; ++l) {
        #pragma unroll
        for (int a = 0; a < 3; ++a)
            #pragma unroll
            for (int c = 0; c < 8; ++c)
                #pragma unroll
                for (int d = 0; d < 4; ++d) D[a][c][d] = 0.f;

        // per-(warp,lane) B base; step stride = 4*8*32 = 1024 uint4, nt stride = 32
        const uint4* wpT = g_Wq + ((l * 16) * 4 + w) * (8 * 32) + lane;

        #pragma unroll
        for (int step = 0; step < 16; ++step) {
            uint4 qb[8];
            #pragma unroll
            for (int nt = 0; nt < 8; ++nt)
                qb[nt] = wpT[step * 1024 + nt * 32];
            #pragma unroll
            for (int st = 0; st < 3; ++st) {
                uint4 Ah = AHq[(st * 16 + step) * 32];
                uint4 Al = ALq[(st * 16 + step) * 32];
                #pragma unroll
                for (int nt = 0; nt < 8; ++nt) {
                    MMA(D[st][nt], Ah.x, Ah.y, Ah.z, Ah.w, qb[nt].x, qb[nt].y);
                    MMA(D[st][nt], Ah.x, Ah.y, Ah.z, Ah.w, qb[nt].z, qb[nt].w);
                    MMA(D[st][nt], Al.x, Al.y, Al.z, Al.w, qb[nt].x, qb[nt].y);
                }
            }
        }
        __syncthreads();   // all warps done reading A planes before rewrite

        // ---- jet epilogue ----
        if (l == 1) {
            #pragma unroll
            for (int a = 0; a < 2; ++a)
                #pragma unroll
                for (int c = 0; c < 3; ++c) ps[a][c] = 0.f;
        }
        #pragma unroll
        for (int nt = 0; nt < 8; ++nt) {
            const int u0 = (w << 6) + (nt << 3) + (tid3 << 1);
            float2 bb  = *(const float2*)(biasSm + (l ? 256 : 0) + u0);
            float2 w4v = *(const float2*)(w4Sm + u0);
            float av[4], a1v[4], a2v[4];
            #pragma unroll
            for (int p_ = 0; p_ < 4; ++p_) {
                float z  = D[0][nt][p_] + ((p_ & 1) ? bb.y : bb.x);
                float z1 = D[1][nt][p_];
                float z2 = D[2][nt][p_];
                float a, s2;
                tanh_d(z, a, s2);
                av[p_]  = a;
                a1v[p_] = s2 * z1;
                a2v[p_] = s2 * z2 - 2.f * a * a1v[p_] * z1;
            }
            if (l == 0) {
                const int pi = (w << 5) + (nt << 2) + tid3;   // k-pair index
                const int step_t = pi >> 3, o = pi & 7;
                const int wsel = (o & 4) ? 2 : 0;
                const int lane_t = (g4 << 2) | (o & 3);
                uint32_t hA, lA, hB, lB;
                #pragma unroll
                for (int st = 0; st < 3; ++st) {
                    const float* v = (st == 0) ? av : (st == 1) ? a1v : a2v;
                    pk2(v[0], v[1], hA, lA);      // row g4
                    pk2(v[2], v[3], hB, lB);      // row g4+8
                    const int base = ((st * 16 + step_t) * 32 + lane_t) * 4 + wsel;
                    *(uint2*)(AH + base) = make_uint2(hA, hB);
                    *(uint2*)(AL + base) = make_uint2(lA, lB);
                }
            } else {
                #pragma unroll
                for (int p_ = 0; p_ < 4; ++p_) {
                    float wv = (p_ & 1) ? w4v.y : w4v.x;
                    int rh = p_ >> 1;
                    ps[rh][0] += av[p_]  * wv;
                    ps[rh][1] += a1v[p_] * wv;
                    ps[rh][2] += a2v[p_] * wv;
                }
            }
        }
        if (l == 0) {
            __syncthreads();           // A planes fully rewritten before layer-2
        } else {
            #pragma unroll
            for (int rh = 0; rh < 2; ++rh)
                #pragma unroll
                for (int st = 0; st < 3; ++st) {
                    float v = ps[rh][st];
                    v += __shfl_xor_sync(0xffffffffu, v, 1);
                    v += __shfl_xor_sync(0xffffffffu, v, 2);
                    if (tid3 == 0)
                        atomicAdd(&outSm[st * 16 + g4 + rh * 8], v);
                }
        }
    }

    __syncthreads();
    if (t < 48) {
        int st = t >> 4, s = t & 15;
        float v = outSm[t] + (st == 0 ? b4[0] : 0.f);
        out[st * B + bs + s] = v;
    }
}

extern "C" void kernel_launch(void* const* d_in, const int* in_sizes, int n_in,
                              void* d_out, int out_size) {
    const float* x  = (const float*)d_in[0];
    const float* W1 = (const float*)d_in[1];
    const float* b1 = (const float*)d_in[2];
    const float* W2 = (const float*)d_in[3];
    const float* b2 = (const float*)d_in[4];
    const float* W3 = (const float*)d_in[5];
    const float* b3 = (const float*)d_in[6];
    const float* W4 = (const float*)d_in[7];
    const float* b4 = (const float*)d_in[8];
    float* out = (float*)d_out;
    const int B = in_sizes[0] / 2;

    prep_w<<<32, 128>>>(W2, W3);

    cudaFuncSetAttribute(pinn_mma_kernel,
                         cudaFuncAttributeMaxDynamicSharedMemorySize, SM_TOT);
    pinn_mma_kernel<<<B / 16, 128, SM_TOT>>>(x, W1, b1, b2, b3, W4, b4, out, B);
}